// round 13
// baseline (speedup 1.0000x reference)
#include <cuda_runtime.h>
#include <cstdint>

// ---------------- scratch (no cudaMalloc allowed) ----------------
#define ELEMS 33554432
__device__ float g_q[ELEMS];
__device__ float g_k[ELEMS];
__device__ float g_v[ELEMS];
__device__ float g_ao[ELEMS];
// pre-rounded tf32 weights
__device__ float g_wq[65536];
__device__ float g_wk[65536];
__device__ float g_wv[65536];
__device__ float g_wo[262144];

// ---------------- helpers ----------------
__device__ __forceinline__ uint32_t f2tf(float x) {
    uint32_t r;
    asm("cvt.rna.tf32.f32 %0, %1;" : "=r"(r) : "f"(x));
    return r;
}
__device__ __forceinline__ float f2tf_f(float x) {
    return __uint_as_float(f2tf(x));
}

__device__ __forceinline__ void mma8(float* d, const uint32_t* a, const uint32_t* b) {
    asm volatile(
        "mma.sync.aligned.m16n8k8.row.col.f32.tf32.tf32.f32 "
        "{%0,%1,%2,%3}, {%4,%5,%6,%7}, {%8,%9}, {%0,%1,%2,%3};"
        : "+f"(d[0]), "+f"(d[1]), "+f"(d[2]), "+f"(d[3])
        : "r"(a[0]), "r"(a[1]), "r"(a[2]), "r"(a[3]), "r"(b[0]), "r"(b[1]));
}

__device__ __forceinline__ uint32_t smem_u32(const void* p) {
    return (uint32_t)__cvta_generic_to_shared(p);
}
__device__ __forceinline__ void cp16(uint32_t dst, const void* src) {
    asm volatile("cp.async.cg.shared.global [%0], [%1], 16;" :: "r"(dst), "l"(src));
}
__device__ __forceinline__ void cp_commit() {
    asm volatile("cp.async.commit_group;");
}
template <int N>
__device__ __forceinline__ void cp_wait() {
    asm volatile("cp.async.wait_group %0;" :: "n"(N));
}

// ---------------- weight prep: round to tf32 once ----------------
__global__ void prep_weights_kernel(
    const float* __restrict__ Wq, const float* __restrict__ Wk,
    const float* __restrict__ Wv, const float* __restrict__ Wo)
{
    int i = blockIdx.x * 256 + threadIdx.x;     // 0..262143
    if (i < 65536) {
        g_wq[i] = f2tf_f(Wq[i]);
        g_wk[i] = f2tf_f(Wk[i]);
        g_wv[i] = f2tf_f(Wv[i]);
    }
    g_wo[i] = f2tf_f(Wo[i]);
}

// ================= projection GEMM: C = A @ W + bias ========================
// CTA tile 128x128, 128 threads = 4 warps, warp tile 64x64 (2x2 warp grid).
// BK=32 (4 k-steps per barrier window), 3-stage cp.async, 1 sync per tile.
#define AS_STRIDE 36   // 32 + 4 pad (stride ≡ 4 mod 32: conflict-free A frags)
#define BS_STRIDE 136  // 128 + 8 pad
#define STAGE_F (128 * AS_STRIDE + 32 * BS_STRIDE)   // 8960 floats / stage
#define GEMM_SMEM (3 * STAGE_F * 4)                  // 107520 B

template <bool CVT_A, bool ROUND_OUT>
__device__ __forceinline__ void gemm_body(
    const float* __restrict__ A, const float* __restrict__ W,
    const float* __restrict__ bias, float* __restrict__ C,
    int N, int K)
{
    extern __shared__ float smem[];

    int tid  = threadIdx.x;
    int lane = tid & 31, warp = tid >> 5;   // warp 0..3
    int g = lane >> 2, t = lane & 3;
    int wm = (warp & 1) * 64;               // warp row base
    int wn = (warp >> 1) * 64;              // warp col base
    int m0 = blockIdx.y * 128;
    int n0 = blockIdx.x * 128;

    // per-thread cp.async slots: 8 A chunks + 8 B chunks (128 threads)
    int ar[8], ac[8], br[8], bc[8];
    #pragma unroll
    for (int i = 0; i < 8; i++) {
        int f = tid + i * 128;
        ar[i] = f >> 3; ac[i] = (f & 7) * 4;
        br[i] = f >> 5; bc[i] = (f & 31) * 4;
    }

    int nTiles = K / 32;

    auto issue = [&](int tile) {
        if (tile < nTiles) {
            float* st = &smem[(tile % 3) * STAGE_F];
            float* stb = st + 128 * AS_STRIDE;
            int kc = tile * 32;
            #pragma unroll
            for (int i = 0; i < 8; i++)
                cp16(smem_u32(&st[ar[i] * AS_STRIDE + ac[i]]),
                     &A[(size_t)(m0 + ar[i]) * K + kc + ac[i]]);
            #pragma unroll
            for (int i = 0; i < 8; i++)
                cp16(smem_u32(&stb[br[i] * BS_STRIDE + bc[i]]),
                     &W[(size_t)(kc + br[i]) * N + n0 + bc[i]]);
        }
        cp_commit();
    };

    float acc[4][8][4] = {};

    issue(0);
    issue(1);

    for (int i = 0; i < nTiles; i++) {
        cp_wait<1>();             // tile i resident
        __syncthreads();          // visible to all; compute(i-1) done by all

        const float* As = &smem[(i % 3) * STAGE_F];
        const float* Bs = As + 128 * AS_STRIDE;

        #pragma unroll
        for (int ks = 0; ks < 4; ks++) {
            int k0 = ks * 8;
            uint32_t a[4][4], b[8][2];
            #pragma unroll
            for (int mt = 0; mt < 4; mt++) {
                int r = wm + 16 * mt + g;
                if (CVT_A) {
                    a[mt][0] = f2tf(As[r * AS_STRIDE + k0 + t]);
                    a[mt][1] = f2tf(As[(r + 8) * AS_STRIDE + k0 + t]);
                    a[mt][2] = f2tf(As[r * AS_STRIDE + k0 + 4 + t]);
                    a[mt][3] = f2tf(As[(r + 8) * AS_STRIDE + k0 + 4 + t]);
                } else {
                    a[mt][0] = __float_as_uint(As[r * AS_STRIDE + k0 + t]);
                    a[mt][1] = __float_as_uint(As[(r + 8) * AS_STRIDE + k0 + t]);
                    a[mt][2] = __float_as_uint(As[r * AS_STRIDE + k0 + 4 + t]);
                    a[mt][3] = __float_as_uint(As[(r + 8) * AS_STRIDE + k0 + 4 + t]);
                }
            }
            #pragma unroll
            for (int nt = 0; nt < 8; nt++) {
                int cb = wn + 8 * nt + g;
                b[nt][0] = __float_as_uint(Bs[(k0 + t) * BS_STRIDE + cb]);
                b[nt][1] = __float_as_uint(Bs[(k0 + 4 + t) * BS_STRIDE + cb]);
            }
            #pragma unroll
            for (int mt = 0; mt < 4; mt++)
                #pragma unroll
                for (int nt = 0; nt < 8; nt++)
                    mma8(acc[mt][nt], a[mt], b[nt]);
        }

        issue(i + 2);             // overwrites stage (i-1): safe after the sync
    }

    #pragma unroll
    for (int mt = 0; mt < 4; mt++) {
        int r0 = m0 + wm + 16 * mt + g;
        #pragma unroll
        for (int nt = 0; nt < 8; nt++) {
            int col = n0 + wn + 8 * nt + 2 * t;
            float b0 = bias[col], b1 = bias[col + 1];
            float2 v0, v1;
            if (ROUND_OUT) {
                v0 = {f2tf_f(acc[mt][nt][0] + b0), f2tf_f(acc[mt][nt][1] + b1)};
                v1 = {f2tf_f(acc[mt][nt][2] + b0), f2tf_f(acc[mt][nt][3] + b1)};
            } else {
                v0 = {acc[mt][nt][0] + b0, acc[mt][nt][1] + b1};
                v1 = {acc[mt][nt][2] + b0, acc[mt][nt][3] + b1};
            }
            *(float2*)&C[(size_t)r0 * N + col] = v0;
            *(float2*)&C[(size_t)(r0 + 8) * N + col] = v1;
        }
    }
}

__global__ __launch_bounds__(128, 2) void qkv_proj_kernel(
    const float* __restrict__ qin, const float* __restrict__ kin,
    const float* __restrict__ vin,
    const float* __restrict__ bq, const float* __restrict__ bk,
    const float* __restrict__ bv)
{
    const float* A; const float* W; const float* bias; float* C;
    if (blockIdx.z == 0)      { A = qin; W = g_wq; bias = bq; C = g_q; }
    else if (blockIdx.z == 1) { A = kin; W = g_wk; bias = bk; C = g_k; }
    else                      { A = vin; W = g_wv; bias = bv; C = g_v; }
    gemm_body<true, true>(A, W, bias, C, 512, 128);
}

__global__ __launch_bounds__(128, 2) void out_proj_kernel(
    const float* __restrict__ bo, float* __restrict__ out)
{
    gemm_body<false, false>(g_ao, g_wo, bo, out, 512, 512);
}

// ================= attention (unchanged from round 10) ======================
#define KS_STRIDE 68
#define VS_STRIDE 72
#define PB_STRIDE 68
#define K_STAGE_F (64 * KS_STRIDE)
#define V_STAGE_F (64 * VS_STRIDE)
#define ATTN_SMEM ((2 * K_STAGE_F + 2 * V_STAGE_F + 8 * 16 * PB_STRIDE) * 4) // 106496 B

__global__ __launch_bounds__(256, 2) void attn_kernel()
{
    extern __shared__ float sm[];
    float* Kst = sm;
    float* Vst = sm + 2 * K_STAGE_F;
    float* PbA = sm + 2 * K_STAGE_F + 2 * V_STAGE_F;

    int tid = threadIdx.x, lane = tid & 31, warp = tid >> 5;
    int g = lane >> 2, t = lane & 3;
    uint32_t* Pb = (uint32_t*)(PbA + warp * (16 * PB_STRIDE));

    int h  = blockIdx.x;
    int bn = blockIdx.y;
    int half = blockIdx.z;
    size_t base  = (size_t)bn * 131072 + (size_t)h * 64;
    size_t baseq = base + (size_t)half * 128 * 512;

    int f0 = tid, f1 = tid + 256, f2 = tid + 512, f3 = tid + 768;
    int r0 = f0 >> 4, c0 = (f0 & 15) * 4;
    int r1 = f1 >> 4, c1 = (f1 & 15) * 4;
    int r2 = f2 >> 4, c2 = (f2 & 15) * 4;
    int r3 = f3 >> 4, c3 = (f3 & 15) * 4;

    auto issue = [&](int chunk) {
        if (chunk < 4) {
            int kb = chunk * 64;
            float* Kd = Kst + (chunk & 1) * K_STAGE_F;
            float* Vd = Vst + (chunk & 1) * V_STAGE_F;
            cp16(smem_u32(&Kd[r0 * KS_STRIDE + c0]), &g_k[base + (size_t)(kb + r0) * 512 + c0]);
            cp16(smem_u32(&Kd[r1 * KS_STRIDE + c1]), &g_k[base + (size_t)(kb + r1) * 512 + c1]);
            cp16(smem_u32(&Kd[r2 * KS_STRIDE + c2]), &g_k[base + (size_t)(kb + r2) * 512 + c2]);
            cp16(smem_u32(&Kd[r3 * KS_STRIDE + c3]), &g_k[base + (size_t)(kb + r3) * 512 + c3]);
            cp16(smem_u32(&Vd[r0 * VS_STRIDE + c0]), &g_v[base + (size_t)(kb + r0) * 512 + c0]);
            cp16(smem_u32(&Vd[r1 * VS_STRIDE + c1]), &g_v[base + (size_t)(kb + r1) * 512 + c1]);
            cp16(smem_u32(&Vd[r2 * VS_STRIDE + c2]), &g_v[base + (size_t)(kb + r2) * 512 + c2]);
            cp16(smem_u32(&Vd[r3 * VS_STRIDE + c3]), &g_v[base + (size_t)(kb + r3) * 512 + c3]);
        }
        cp_commit();
    };

    issue(0);
    issue(1);

    // Q tile: warp's 16 rows x 64 cols; g_q pre-rounded, *0.125 is exact
    int qr0 = warp * 16;
    #pragma unroll
    for (int i = 0; i < 8; i++) {
        int f = lane + i * 32;
        int r = f >> 4, c4 = (f & 15) * 4;
        float4 qv = *(const float4*)&g_q[baseq + (size_t)(qr0 + r) * 512 + c4];
        Pb[r * PB_STRIDE + c4 + 0] = __float_as_uint(qv.x * 0.125f);
        Pb[r * PB_STRIDE + c4 + 1] = __float_as_uint(qv.y * 0.125f);
        Pb[r * PB_STRIDE + c4 + 2] = __float_as_uint(qv.z * 0.125f);
        Pb[r * PB_STRIDE + c4 + 3] = __float_as_uint(qv.w * 0.125f);
    }
    __syncwarp();

    uint32_t q[8][4];
    #pragma unroll
    for (int ks = 0; ks < 8; ks++) {
        int k0 = 8 * ks;
        q[ks][0] = Pb[g * PB_STRIDE + k0 + t];
        q[ks][1] = Pb[(g + 8) * PB_STRIDE + k0 + t];
        q[ks][2] = Pb[g * PB_STRIDE + k0 + 4 + t];
        q[ks][3] = Pb[(g + 8) * PB_STRIDE + k0 + 4 + t];
    }
    __syncwarp();

    float o[8][4] = {};
    float den0 = 0.0f, den1 = 0.0f;

    #pragma unroll 1
    for (int c = 0; c < 4; c++) {
        cp_wait<1>();
        __syncthreads();
        const float* Ks = Kst + (c & 1) * K_STAGE_F;
        const float* Vs = Vst + (c & 1) * V_STAGE_F;

        // ---- S = Q K_chunk^T ----
        float s[8][4] = {};
        #pragma unroll
        for (int ks = 0; ks < 8; ks++) {
            int k0 = 8 * ks;
            uint32_t b[8][2];
            #pragma unroll
            for (int nt = 0; nt < 8; nt++) {
                int kr = 8 * nt + g;
                b[nt][0] = __float_as_uint(Ks[kr * KS_STRIDE + k0 + t]);
                b[nt][1] = __float_as_uint(Ks[kr * KS_STRIDE + k0 + 4 + t]);
            }
            #pragma unroll
            for (int nt = 0; nt < 8; nt++)
                mma8(s[nt], q[ks], b[nt]);
        }

        // ---- exp, denom, P -> Pb ----
        #pragma unroll
        for (int nt = 0; nt < 8; nt++) {
            float e0 = __expf(s[nt][0]);
            float e1 = __expf(s[nt][1]);
            float e2 = __expf(s[nt][2]);
            float e3 = __expf(s[nt][3]);
            den0 += e0 + e1;
            den1 += e2 + e3;
            int cc = 8 * nt + 2 * t;
            uint2 p0 = {f2tf(e0), f2tf(e1)};
            uint2 p1 = {f2tf(e2), f2tf(e3)};
            *(uint2*)&Pb[g * PB_STRIDE + cc] = p0;
            *(uint2*)&Pb[(g + 8) * PB_STRIDE + cc] = p1;
        }
        __syncwarp();

        // ---- O += P V_chunk ----
        #pragma unroll
        for (int ks = 0; ks < 8; ks++) {
            int k0 = 8 * ks;
            uint32_t pa[4], b[8][2];
            pa[0] = Pb[g * PB_STRIDE + k0 + t];
            pa[1] = Pb[(g + 8) * PB_STRIDE + k0 + t];
            pa[2] = Pb[g * PB_STRIDE + k0 + 4 + t];
            pa[3] = Pb[(g + 8) * PB_STRIDE + k0 + 4 + t];
            #pragma unroll
            for (int nt = 0; nt < 8; nt++) {
                b[nt][0] = __float_as_uint(Vs[(k0 + t) * VS_STRIDE + 8 * nt + g]);
                b[nt][1] = __float_as_uint(Vs[(k0 + 4 + t) * VS_STRIDE + 8 * nt + g]);
            }
            #pragma unroll
            for (int nt = 0; nt < 8; nt++)
                mma8(o[nt], pa, b[nt]);
        }

        __syncthreads();
        issue(c + 2);
    }

    // ---- normalize, store tf32-rounded (consumed by out_proj raw) ----
    den0 += __shfl_xor_sync(0xffffffffu, den0, 1);
    den0 += __shfl_xor_sync(0xffffffffu, den0, 2);
    den1 += __shfl_xor_sync(0xffffffffu, den1, 1);
    den1 += __shfl_xor_sync(0xffffffffu, den1, 2);
    float inv0 = 1.0f / den0, inv1 = 1.0f / den1;

    int rg = qr0 + g;
    #pragma unroll
    for (int nt = 0; nt < 8; nt++) {
        int col = 8 * nt + 2 * t;
        float2 v0 = {f2tf_f(o[nt][0] * inv0), f2tf_f(o[nt][1] * inv0)};
        float2 v1 = {f2tf_f(o[nt][2] * inv1), f2tf_f(o[nt][3] * inv1)};
        *(float2*)&g_ao[baseq + (size_t)rg * 512 + col] = v0;
        *(float2*)&g_ao[baseq + (size_t)(rg + 8) * 512 + col] = v1;
    }
}

extern "C" void kernel_launch(void* const* d_in, const int* in_sizes, int n_in,
                              void* d_out, int out_size)
{
    const float* query = (const float*)d_in[0];
    const float* key   = (const float*)d_in[1];
    const float* value = (const float*)d_in[2];
    const float* Wq    = (const float*)d_in[3];
    const float* bq    = (const float*)d_in[4];
    const float* Wk    = (const float*)d_in[5];
    const float* bk    = (const float*)d_in[6];
    const float* Wv    = (const float*)d_in[7];
    const float* bv    = (const float*)d_in[8];
    const float* Wo    = (const float*)d_in[9];
    const float* bo    = (const float*)d_in[10];
    float* out = (float*)d_out;

    prep_weights_kernel<<<1024, 256>>>(Wq, Wk, Wv, Wo);

    cudaFuncSetAttribute(qkv_proj_kernel,
                         cudaFuncAttributeMaxDynamicSharedMemorySize, GEMM_SMEM);
    cudaFuncSetAttribute(out_proj_kernel,
                         cudaFuncAttributeMaxDynamicSharedMemorySize, GEMM_SMEM);

    dim3 gproj(512 / 128, 65536 / 128, 3);
    qkv_proj_kernel<<<gproj, 128, GEMM_SMEM>>>(query, key, value, bq, bk, bv);

    cudaFuncSetAttribute(attn_kernel,
                         cudaFuncAttributeMaxDynamicSharedMemorySize, ATTN_SMEM);
    dim3 gattn(8, 256, 2);
    attn_kernel<<<gattn, 256, ATTN_SMEM>>>();

    dim3 gout(512 / 128, 65536 / 128);
    out_proj_kernel<<<gout, 128, GEMM_SMEM>>>(bo, out);
}

// round 15
// speedup vs baseline: 1.8841x; 1.8841x over previous
#include <cuda_runtime.h>
#include <cuda_fp16.h>
#include <cstdint>

// ---------------- scratch (no cudaMalloc allowed) ----------------
#define ELEMS 33554432           // B*N*L*512
#define IN_ELEMS 8388608         // B*N*L*128
__device__ float g_q[ELEMS];
__device__ float g_k[ELEMS];
__device__ float g_v[ELEMS];
__device__ __half g_ao[ELEMS];                 // attention out, fp16
__device__ __half g_inq[IN_ELEMS];             // fp16 inputs
__device__ __half g_ink[IN_ELEMS];
__device__ __half g_inv[IN_ELEMS];
__device__ __half g_wqt[65536];                // W^T [n=512][k=128] fp16
__device__ __half g_wkt[65536];
__device__ __half g_wvt[65536];
__device__ __half g_wot[262144];               // Wo^T [n=512][k=512] fp16

// ---------------- helpers ----------------
__device__ __forceinline__ uint32_t f2tf(float x) {
    uint32_t r;
    asm("cvt.rna.tf32.f32 %0, %1;" : "=r"(r) : "f"(x));
    return r;
}
__device__ __forceinline__ float f2tf_f(float x) {
    return __uint_as_float(f2tf(x));
}

__device__ __forceinline__ void mma8(float* d, const uint32_t* a, const uint32_t* b) {
    asm volatile(
        "mma.sync.aligned.m16n8k8.row.col.f32.tf32.tf32.f32 "
        "{%0,%1,%2,%3}, {%4,%5,%6,%7}, {%8,%9}, {%0,%1,%2,%3};"
        : "+f"(d[0]), "+f"(d[1]), "+f"(d[2]), "+f"(d[3])
        : "r"(a[0]), "r"(a[1]), "r"(a[2]), "r"(a[3]), "r"(b[0]), "r"(b[1]));
}
__device__ __forceinline__ void mma16(float* d, const uint32_t* a, const uint32_t* b) {
    asm volatile(
        "mma.sync.aligned.m16n8k16.row.col.f32.f16.f16.f32 "
        "{%0,%1,%2,%3}, {%4,%5,%6,%7}, {%8,%9}, {%0,%1,%2,%3};"
        : "+f"(d[0]), "+f"(d[1]), "+f"(d[2]), "+f"(d[3])
        : "r"(a[0]), "r"(a[1]), "r"(a[2]), "r"(a[3]), "r"(b[0]), "r"(b[1]));
}

__device__ __forceinline__ uint32_t smem_u32(const void* p) {
    return (uint32_t)__cvta_generic_to_shared(p);
}
__device__ __forceinline__ void cp16(uint32_t dst, const void* src) {
    asm volatile("cp.async.cg.shared.global [%0], [%1], 16;" :: "r"(dst), "l"(src));
}
__device__ __forceinline__ void cp_commit() {
    asm volatile("cp.async.commit_group;");
}
template <int N>
__device__ __forceinline__ void cp_wait() {
    asm volatile("cp.async.wait_group %0;" :: "n"(N));
}

// ---------------- prep kernels ----------------
// fp32 inputs -> fp16
__global__ void prep_inputs_kernel(
    const float* __restrict__ q, const float* __restrict__ k,
    const float* __restrict__ v)
{
    int i4 = (blockIdx.x * 256 + threadIdx.x) * 4;   // < IN_ELEMS
    float4 a = *(const float4*)&q[i4];
    float4 b = *(const float4*)&k[i4];
    float4 c = *(const float4*)&v[i4];
    __half2 h[2];
    h[0] = __floats2half2_rn(a.x, a.y); h[1] = __floats2half2_rn(a.z, a.w);
    *(uint2*)&g_inq[i4] = *(uint2*)h;
    h[0] = __floats2half2_rn(b.x, b.y); h[1] = __floats2half2_rn(b.z, b.w);
    *(uint2*)&g_ink[i4] = *(uint2*)h;
    h[0] = __floats2half2_rn(c.x, c.y); h[1] = __floats2half2_rn(c.z, c.w);
    *(uint2*)&g_inv[i4] = *(uint2*)h;
}

// qkv weights [k=128][n=512] -> transposed fp16 [n][k]
__global__ void prep_wqkv_kernel(
    const float* __restrict__ Wq, const float* __restrict__ Wk,
    const float* __restrict__ Wv)
{
    __shared__ float tile[32][33];
    const float* W = (blockIdx.z == 0) ? Wq : (blockIdx.z == 1) ? Wk : Wv;
    __half* Wt = (blockIdx.z == 0) ? g_wqt : (blockIdx.z == 1) ? g_wkt : g_wvt;
    int kt = blockIdx.y * 32, nt = blockIdx.x * 32;
    int tx = threadIdx.x, ty = threadIdx.y;
    tile[ty][tx] = W[(size_t)(kt + ty) * 512 + nt + tx];
    __syncthreads();
    Wt[(nt + ty) * 128 + kt + tx] = __float2half_rn(tile[tx][ty]);
}

// Wo [k=512][n=512] -> transposed fp16 [n][k]
__global__ void prep_wo_kernel(const float* __restrict__ Wo)
{
    __shared__ float tile[32][33];
    int kt = blockIdx.y * 32, nt = blockIdx.x * 32;
    int tx = threadIdx.x, ty = threadIdx.y;
    tile[ty][tx] = Wo[(size_t)(kt + ty) * 512 + nt + tx];
    __syncthreads();
    g_wot[(nt + ty) * 512 + kt + tx] = __float2half_rn(tile[tx][ty]);
}

// ================= fp16 GEMM: C[M,N] = A[M,K] @ Wt[N,K]^T + bias ============
// CTA 128x128 tile, 128 threads = 4 warps (2x2), warp tile 64x64.
// BK=64 halves per stage (4 k16-steps), 3-stage cp.async, 1 sync/tile.
// smem rows: 72 halves = 144 B (== 16 mod 128 -> conflict-free frag loads).
#define HS_STRIDE 72
#define HSTAGE_B (2 * 128 * HS_STRIDE * 2)      // A + W tiles, bytes = 36864
#define HGEMM_SMEM (3 * HSTAGE_B)               // 110592 B

template <bool ROUND_OUT>
__device__ __forceinline__ void hgemm_body(
    const __half* __restrict__ A, const __half* __restrict__ Wt,
    const float* __restrict__ bias, float* __restrict__ C,
    int N, int K)
{
    extern __shared__ char hsm[];

    int tid  = threadIdx.x;
    int lane = tid & 31, warp = tid >> 5;
    int g = lane >> 2, t = lane & 3;
    int wm = (warp & 1) * 64;
    int wn = (warp >> 1) * 64;
    int m0 = blockIdx.y * 128;
    int n0 = blockIdx.x * 128;

    // cp.async slots: per stage 2 tensors x 128 rows x 8 16B-chunks = 2048
    int tr[16], tc[16], tt[16];
    #pragma unroll
    for (int i = 0; i < 16; i++) {
        int ci = tid + i * 128;
        tt[i] = ci >> 10;           // 0 = A, 1 = W
        int w = ci & 1023;
        tr[i] = w >> 3; tc[i] = w & 7;
    }

    int nTiles = K / 64;

    auto issue = [&](int tile) {
        if (tile < nTiles) {
            uint32_t stb = smem_u32(hsm) + (tile % 3) * HSTAGE_B;
            int kc = tile * 64;
            #pragma unroll
            for (int i = 0; i < 16; i++) {
                uint32_t dst = stb + (uint32_t)tt[i] * (128 * HS_STRIDE * 2)
                             + (uint32_t)(tr[i] * (HS_STRIDE * 2) + tc[i] * 16);
                const __half* src = tt[i] == 0
                    ? &A[(size_t)(m0 + tr[i]) * K + kc + tc[i] * 8]
                    : &Wt[(size_t)(n0 + tr[i]) * K + kc + tc[i] * 8];
                cp16(dst, src);
            }
        }
        cp_commit();
    };

    float acc[4][8][4] = {};

    issue(0);
    issue(1);

    for (int i = 0; i < nTiles; i++) {
        cp_wait<1>();
        __syncthreads();

        const char* As = hsm + (i % 3) * HSTAGE_B;
        const char* Bs = As + 128 * HS_STRIDE * 2;

        #pragma unroll
        for (int ks = 0; ks < 4; ks++) {
            int kb = ks * 32 + 4 * t;          // byte offset of k-cols 16ks+2t
            uint32_t a[4][4], b[8][2];
            #pragma unroll
            for (int mt = 0; mt < 4; mt++) {
                int r = wm + 16 * mt + g;
                const char* row0 = As + r * (HS_STRIDE * 2);
                const char* row8 = As + (r + 8) * (HS_STRIDE * 2);
                a[mt][0] = *(const uint32_t*)(row0 + kb);
                a[mt][1] = *(const uint32_t*)(row8 + kb);
                a[mt][2] = *(const uint32_t*)(row0 + kb + 16);
                a[mt][3] = *(const uint32_t*)(row8 + kb + 16);
            }
            #pragma unroll
            for (int nt = 0; nt < 8; nt++) {
                const char* rw = Bs + (wn + 8 * nt + g) * (HS_STRIDE * 2);
                b[nt][0] = *(const uint32_t*)(rw + kb);
                b[nt][1] = *(const uint32_t*)(rw + kb + 16);
            }
            #pragma unroll
            for (int mt = 0; mt < 4; mt++)
                #pragma unroll
                for (int nt = 0; nt < 8; nt++)
                    mma16(acc[mt][nt], a[mt], b[nt]);
        }

        issue(i + 2);
    }

    #pragma unroll
    for (int mt = 0; mt < 4; mt++) {
        int r0 = m0 + wm + 16 * mt + g;
        #pragma unroll
        for (int nt = 0; nt < 8; nt++) {
            int col = n0 + wn + 8 * nt + 2 * t;
            float b0 = bias[col], b1 = bias[col + 1];
            float2 v0, v1;
            if (ROUND_OUT) {
                v0 = {f2tf_f(acc[mt][nt][0] + b0), f2tf_f(acc[mt][nt][1] + b1)};
                v1 = {f2tf_f(acc[mt][nt][2] + b0), f2tf_f(acc[mt][nt][3] + b1)};
            } else {
                v0 = {acc[mt][nt][0] + b0, acc[mt][nt][1] + b1};
                v1 = {acc[mt][nt][2] + b0, acc[mt][nt][3] + b1};
            }
            *(float2*)&C[(size_t)r0 * N + col] = v0;
            *(float2*)&C[(size_t)(r0 + 8) * N + col] = v1;
        }
    }
}

__global__ __launch_bounds__(128, 2) void qkv_proj_kernel(
    const float* __restrict__ bq, const float* __restrict__ bk,
    const float* __restrict__ bv)
{
    const __half* A; const __half* Wt; const float* bias; float* C;
    if (blockIdx.z == 0)      { A = g_inq; Wt = g_wqt; bias = bq; C = g_q; }
    else if (blockIdx.z == 1) { A = g_ink; Wt = g_wkt; bias = bk; C = g_k; }
    else                      { A = g_inv; Wt = g_wvt; bias = bv; C = g_v; }
    hgemm_body<true>(A, Wt, bias, C, 512, 128);
}

__global__ __launch_bounds__(128, 2) void out_proj_kernel(
    const float* __restrict__ bo, float* __restrict__ out)
{
    hgemm_body<false>(g_ao, g_wot, bo, out, 512, 512);
}

// ================= attention (round-11 proven; fp16 output) =================
#define KS_STRIDE 68
#define VS_STRIDE 72
#define PB_STRIDE 68
#define K_STAGE_F (64 * KS_STRIDE)
#define V_STAGE_F (64 * VS_STRIDE)
#define ATTN_SMEM ((2 * K_STAGE_F + 2 * V_STAGE_F + 8 * 16 * PB_STRIDE) * 4) // 106496 B

__global__ __launch_bounds__(256, 2) void attn_kernel()
{
    extern __shared__ float sm[];
    float* Kst = sm;
    float* Vst = sm + 2 * K_STAGE_F;
    float* PbA = sm + 2 * K_STAGE_F + 2 * V_STAGE_F;

    int tid = threadIdx.x, lane = tid & 31, warp = tid >> 5;
    int g = lane >> 2, t = lane & 3;
    uint32_t* Pb = (uint32_t*)(PbA + warp * (16 * PB_STRIDE));

    int h  = blockIdx.x;
    int bn = blockIdx.y;
    int half_ = blockIdx.z;
    size_t base  = (size_t)bn * 131072 + (size_t)h * 64;
    size_t baseq = base + (size_t)half_ * 128 * 512;

    int f0 = tid, f1 = tid + 256, f2 = tid + 512, f3 = tid + 768;
    int r0 = f0 >> 4, c0 = (f0 & 15) * 4;
    int r1 = f1 >> 4, c1 = (f1 & 15) * 4;
    int r2 = f2 >> 4, c2 = (f2 & 15) * 4;
    int r3 = f3 >> 4, c3 = (f3 & 15) * 4;

    auto issue = [&](int chunk) {
        if (chunk < 4) {
            int kb = chunk * 64;
            float* Kd = Kst + (chunk & 1) * K_STAGE_F;
            float* Vd = Vst + (chunk & 1) * V_STAGE_F;
            cp16(smem_u32(&Kd[r0 * KS_STRIDE + c0]), &g_k[base + (size_t)(kb + r0) * 512 + c0]);
            cp16(smem_u32(&Kd[r1 * KS_STRIDE + c1]), &g_k[base + (size_t)(kb + r1) * 512 + c1]);
            cp16(smem_u32(&Kd[r2 * KS_STRIDE + c2]), &g_k[base + (size_t)(kb + r2) * 512 + c2]);
            cp16(smem_u32(&Kd[r3 * KS_STRIDE + c3]), &g_k[base + (size_t)(kb + r3) * 512 + c3]);
            cp16(smem_u32(&Vd[r0 * VS_STRIDE + c0]), &g_v[base + (size_t)(kb + r0) * 512 + c0]);
            cp16(smem_u32(&Vd[r1 * VS_STRIDE + c1]), &g_v[base + (size_t)(kb + r1) * 512 + c1]);
            cp16(smem_u32(&Vd[r2 * VS_STRIDE + c2]), &g_v[base + (size_t)(kb + r2) * 512 + c2]);
            cp16(smem_u32(&Vd[r3 * VS_STRIDE + c3]), &g_v[base + (size_t)(kb + r3) * 512 + c3]);
        }
        cp_commit();
    };

    issue(0);
    issue(1);

    int qr0 = warp * 16;
    #pragma unroll
    for (int i = 0; i < 8; i++) {
        int f = lane + i * 32;
        int r = f >> 4, c4 = (f & 15) * 4;
        float4 qv = *(const float4*)&g_q[baseq + (size_t)(qr0 + r) * 512 + c4];
        Pb[r * PB_STRIDE + c4 + 0] = __float_as_uint(qv.x * 0.125f);
        Pb[r * PB_STRIDE + c4 + 1] = __float_as_uint(qv.y * 0.125f);
        Pb[r * PB_STRIDE + c4 + 2] = __float_as_uint(qv.z * 0.125f);
        Pb[r * PB_STRIDE + c4 + 3] = __float_as_uint(qv.w * 0.125f);
    }
    __syncwarp();

    uint32_t q[8][4];
    #pragma unroll
    for (int ks = 0; ks < 8; ks++) {
        int k0 = 8 * ks;
        q[ks][0] = Pb[g * PB_STRIDE + k0 + t];
        q[ks][1] = Pb[(g + 8) * PB_STRIDE + k0 + t];
        q[ks][2] = Pb[g * PB_STRIDE + k0 + 4 + t];
        q[ks][3] = Pb[(g + 8) * PB_STRIDE + k0 + 4 + t];
    }
    __syncwarp();

    float o[8][4] = {};
    float den0 = 0.0f, den1 = 0.0f;

    #pragma unroll 1
    for (int c = 0; c < 4; c++) {
        cp_wait<1>();
        __syncthreads();
        const float* Ks = Kst + (c & 1) * K_STAGE_F;
        const float* Vs = Vst + (c & 1) * V_STAGE_F;

        float s[8][4] = {};
        #pragma unroll
        for (int ks = 0; ks < 8; ks++) {
            int k0 = 8 * ks;
            uint32_t b[8][2];
            #pragma unroll
            for (int nt = 0; nt < 8; nt++) {
                int kr = 8 * nt + g;
                b[nt][0] = __float_as_uint(Ks[kr * KS_STRIDE + k0 + t]);
                b[nt][1] = __float_as_uint(Ks[kr * KS_STRIDE + k0 + 4 + t]);
            }
            #pragma unroll
            for (int nt = 0; nt < 8; nt++)
                mma8(s[nt], q[ks], b[nt]);
        }

        #pragma unroll
        for (int nt = 0; nt < 8; nt++) {
            float e0 = __expf(s[nt][0]);
            float e1 = __expf(s[nt][1]);
            float e2 = __expf(s[nt][2]);
            float e3 = __expf(s[nt][3]);
            den0 += e0 + e1;
            den1 += e2 + e3;
            int cc = 8 * nt + 2 * t;
            uint2 p0 = {f2tf(e0), f2tf(e1)};
            uint2 p1 = {f2tf(e2), f2tf(e3)};
            *(uint2*)&Pb[g * PB_STRIDE + cc] = p0;
            *(uint2*)&Pb[(g + 8) * PB_STRIDE + cc] = p1;
        }
        __syncwarp();

        #pragma unroll
        for (int ks = 0; ks < 8; ks++) {
            int k0 = 8 * ks;
            uint32_t pa[4], b[8][2];
            pa[0] = Pb[g * PB_STRIDE + k0 + t];
            pa[1] = Pb[(g + 8) * PB_STRIDE + k0 + t];
            pa[2] = Pb[g * PB_STRIDE + k0 + 4 + t];
            pa[3] = Pb[(g + 8) * PB_STRIDE + k0 + 4 + t];
            #pragma unroll
            for (int nt = 0; nt < 8; nt++) {
                b[nt][0] = __float_as_uint(Vs[(k0 + t) * VS_STRIDE + 8 * nt + g]);
                b[nt][1] = __float_as_uint(Vs[(k0 + 4 + t) * VS_STRIDE + 8 * nt + g]);
            }
            #pragma unroll
            for (int nt = 0; nt < 8; nt++)
                mma8(o[nt], pa, b[nt]);
        }

        __syncthreads();
        issue(c + 2);
    }

    den0 += __shfl_xor_sync(0xffffffffu, den0, 1);
    den0 += __shfl_xor_sync(0xffffffffu, den0, 2);
    den1 += __shfl_xor_sync(0xffffffffu, den1, 1);
    den1 += __shfl_xor_sync(0xffffffffu, den1, 2);
    float inv0 = 1.0f / den0, inv1 = 1.0f / den1;

    int rg = qr0 + g;
    #pragma unroll
    for (int nt = 0; nt < 8; nt++) {
        int col = 8 * nt + 2 * t;
        __half2 h0 = __floats2half2_rn(o[nt][0] * inv0, o[nt][1] * inv0);
        __half2 h1 = __floats2half2_rn(o[nt][2] * inv1, o[nt][3] * inv1);
        *(__half2*)&g_ao[baseq + (size_t)rg * 512 + col] = h0;
        *(__half2*)&g_ao[baseq + (size_t)(rg + 8) * 512 + col] = h1;
    }
}

extern "C" void kernel_launch(void* const* d_in, const int* in_sizes, int n_in,
                              void* d_out, int out_size)
{
    const float* query = (const float*)d_in[0];
    const float* key   = (const float*)d_in[1];
    const float* value = (const float*)d_in[2];
    const float* Wq    = (const float*)d_in[3];
    const float* bq    = (const float*)d_in[4];
    const float* Wk    = (const float*)d_in[5];
    const float* bk    = (const float*)d_in[6];
    const float* Wv    = (const float*)d_in[7];
    const float* bv    = (const float*)d_in[8];
    const float* Wo    = (const float*)d_in[9];
    const float* bo    = (const float*)d_in[10];
    float* out = (float*)d_out;

    prep_inputs_kernel<<<IN_ELEMS / 1024, 256>>>(query, key, value);
    dim3 tb(32, 32);
    prep_wqkv_kernel<<<dim3(16, 4, 3), tb>>>(Wq, Wk, Wv);
    prep_wo_kernel<<<dim3(16, 16), tb>>>(Wo);

    cudaFuncSetAttribute(qkv_proj_kernel,
                         cudaFuncAttributeMaxDynamicSharedMemorySize, HGEMM_SMEM);
    cudaFuncSetAttribute(out_proj_kernel,
                         cudaFuncAttributeMaxDynamicSharedMemorySize, HGEMM_SMEM);

    dim3 gproj(512 / 128, 65536 / 128, 3);
    qkv_proj_kernel<<<gproj, 128, HGEMM_SMEM>>>(bq, bk, bv);

    cudaFuncSetAttribute(attn_kernel,
                         cudaFuncAttributeMaxDynamicSharedMemorySize, ATTN_SMEM);
    dim3 gattn(8, 256, 2);
    attn_kernel<<<gattn, 256, ATTN_SMEM>>>();

    dim3 gout(512 / 128, 65536 / 128);
    out_proj_kernel<<<gout, 128, HGEMM_SMEM>>>(bo, out);
}

// round 16
// speedup vs baseline: 2.4239x; 1.2865x over previous
#include <cuda_runtime.h>
#include <cuda_fp16.h>
#include <cstdint>

// ---------------- scratch (no cudaMalloc allowed) ----------------
#define ELEMS 33554432           // B*N*L*512
#define IN_ELEMS 8388608         // B*N*L*128
__device__ __half g_qh[ELEMS];                 // Q fp16 row-major [token][512]
__device__ __half g_kh[ELEMS];                 // K fp16 row-major
__device__ __half g_vt[ELEMS];                 // V fp16 transposed [bn][h][d][key]
__device__ __half g_ao[ELEMS];                 // attention out fp16
__device__ __half g_inq[IN_ELEMS];             // fp16 inputs
__device__ __half g_ink[IN_ELEMS];
__device__ __half g_inv[IN_ELEMS];
__device__ __half g_wqt[65536];                // W^T [n=512][k=128] fp16
__device__ __half g_wkt[65536];
__device__ __half g_wvt[65536];
__device__ __half g_wot[262144];               // Wo^T [n=512][k=512] fp16

// ---------------- helpers ----------------
__device__ __forceinline__ void mma16(float* d, const uint32_t* a, const uint32_t* b) {
    asm volatile(
        "mma.sync.aligned.m16n8k16.row.col.f32.f16.f16.f32 "
        "{%0,%1,%2,%3}, {%4,%5,%6,%7}, {%8,%9}, {%0,%1,%2,%3};"
        : "+f"(d[0]), "+f"(d[1]), "+f"(d[2]), "+f"(d[3])
        : "r"(a[0]), "r"(a[1]), "r"(a[2]), "r"(a[3]), "r"(b[0]), "r"(b[1]));
}

__device__ __forceinline__ uint32_t smem_u32(const void* p) {
    return (uint32_t)__cvta_generic_to_shared(p);
}
__device__ __forceinline__ void cp16(uint32_t dst, const void* src) {
    asm volatile("cp.async.cg.shared.global [%0], [%1], 16;" :: "r"(dst), "l"(src));
}
__device__ __forceinline__ void cp_commit() {
    asm volatile("cp.async.commit_group;");
}
template <int N>
__device__ __forceinline__ void cp_wait() {
    asm volatile("cp.async.wait_group %0;" :: "n"(N));
}
__device__ __forceinline__ uint32_t h2u(float lo, float hi) {
    __half2 h = __floats2half2_rn(lo, hi);
    return *(uint32_t*)&h;
}

// ---------------- prep kernels ----------------
__global__ void prep_inputs_kernel(
    const float* __restrict__ q, const float* __restrict__ k,
    const float* __restrict__ v)
{
    int i4 = (blockIdx.x * 256 + threadIdx.x) * 4;
    float4 a = *(const float4*)&q[i4];
    float4 b = *(const float4*)&k[i4];
    float4 c = *(const float4*)&v[i4];
    __half2 h[2];
    h[0] = __floats2half2_rn(a.x, a.y); h[1] = __floats2half2_rn(a.z, a.w);
    *(uint2*)&g_inq[i4] = *(uint2*)h;
    h[0] = __floats2half2_rn(b.x, b.y); h[1] = __floats2half2_rn(b.z, b.w);
    *(uint2*)&g_ink[i4] = *(uint2*)h;
    h[0] = __floats2half2_rn(c.x, c.y); h[1] = __floats2half2_rn(c.z, c.w);
    *(uint2*)&g_inv[i4] = *(uint2*)h;
}

__global__ void prep_wqkv_kernel(
    const float* __restrict__ Wq, const float* __restrict__ Wk,
    const float* __restrict__ Wv)
{
    __shared__ float tile[32][33];
    const float* W = (blockIdx.z == 0) ? Wq : (blockIdx.z == 1) ? Wk : Wv;
    __half* Wt = (blockIdx.z == 0) ? g_wqt : (blockIdx.z == 1) ? g_wkt : g_wvt;
    int kt = blockIdx.y * 32, nt = blockIdx.x * 32;
    int tx = threadIdx.x, ty = threadIdx.y;
    tile[ty][tx] = W[(size_t)(kt + ty) * 512 + nt + tx];
    __syncthreads();
    Wt[(nt + ty) * 128 + kt + tx] = __float2half_rn(tile[tx][ty]);
}

__global__ void prep_wo_kernel(const float* __restrict__ Wo)
{
    __shared__ float tile[32][33];
    int kt = blockIdx.y * 32, nt = blockIdx.x * 32;
    int tx = threadIdx.x, ty = threadIdx.y;
    tile[ty][tx] = Wo[(size_t)(kt + ty) * 512 + nt + tx];
    __syncthreads();
    g_wot[(nt + ty) * 512 + kt + tx] = __float2half_rn(tile[tx][ty]);
}

// ================= fp16 GEMM: C = A[M,K] @ Wt[N,K]^T + bias =================
// OUTMODE: 0 = fp32 row-major (final out), 1 = fp16 row-major (Q,K),
//          2 = fp16 V-transposed g_vt[bn][h][d][key]
#define HS_STRIDE 72
#define HSTAGE_B (2 * 128 * HS_STRIDE * 2)
#define HGEMM_SMEM (3 * HSTAGE_B)               // 110592 B

template <int OUTMODE>
__device__ __forceinline__ void hgemm_body(
    const __half* __restrict__ A, const __half* __restrict__ Wt,
    const float* __restrict__ bias, void* __restrict__ Cout,
    int N, int K)
{
    extern __shared__ char hsm[];

    int tid  = threadIdx.x;
    int lane = tid & 31, warp = tid >> 5;
    int g = lane >> 2, t = lane & 3;
    int wm = (warp & 1) * 64;
    int wn = (warp >> 1) * 64;
    int m0 = blockIdx.y * 128;
    int n0 = blockIdx.x * 128;

    int tr[16], tc[16], tt[16];
    #pragma unroll
    for (int i = 0; i < 16; i++) {
        int ci = tid + i * 128;
        tt[i] = ci >> 10;
        int w = ci & 1023;
        tr[i] = w >> 3; tc[i] = w & 7;
    }

    int nTiles = K / 64;

    auto issue = [&](int tile) {
        if (tile < nTiles) {
            uint32_t stb = smem_u32(hsm) + (tile % 3) * HSTAGE_B;
            int kc = tile * 64;
            #pragma unroll
            for (int i = 0; i < 16; i++) {
                uint32_t dst = stb + (uint32_t)tt[i] * (128 * HS_STRIDE * 2)
                             + (uint32_t)(tr[i] * (HS_STRIDE * 2) + tc[i] * 16);
                const __half* src = tt[i] == 0
                    ? &A[(size_t)(m0 + tr[i]) * K + kc + tc[i] * 8]
                    : &Wt[(size_t)(n0 + tr[i]) * K + kc + tc[i] * 8];
                cp16(dst, src);
            }
        }
        cp_commit();
    };

    float acc[4][8][4] = {};

    issue(0);
    issue(1);

    for (int i = 0; i < nTiles; i++) {
        cp_wait<1>();
        __syncthreads();

        const char* As = hsm + (i % 3) * HSTAGE_B;
        const char* Bs = As + 128 * HS_STRIDE * 2;

        #pragma unroll
        for (int ks = 0; ks < 4; ks++) {
            int kb = ks * 32 + 4 * t;
            uint32_t a[4][4], b[8][2];
            #pragma unroll
            for (int mt = 0; mt < 4; mt++) {
                int r = wm + 16 * mt + g;
                const char* row0 = As + r * (HS_STRIDE * 2);
                const char* row8 = As + (r + 8) * (HS_STRIDE * 2);
                a[mt][0] = *(const uint32_t*)(row0 + kb);
                a[mt][1] = *(const uint32_t*)(row8 + kb);
                a[mt][2] = *(const uint32_t*)(row0 + kb + 16);
                a[mt][3] = *(const uint32_t*)(row8 + kb + 16);
            }
            #pragma unroll
            for (int nt = 0; nt < 8; nt++) {
                const char* rw = Bs + (wn + 8 * nt + g) * (HS_STRIDE * 2);
                b[nt][0] = *(const uint32_t*)(rw + kb);
                b[nt][1] = *(const uint32_t*)(rw + kb + 16);
            }
            #pragma unroll
            for (int mt = 0; mt < 4; mt++)
                #pragma unroll
                for (int nt = 0; nt < 8; nt++)
                    mma16(acc[mt][nt], a[mt], b[nt]);
        }

        issue(i + 2);
    }

    #pragma unroll
    for (int mt = 0; mt < 4; mt++) {
        int r0 = m0 + wm + 16 * mt + g;
        #pragma unroll
        for (int nt = 0; nt < 8; nt++) {
            int col = n0 + wn + 8 * nt + 2 * t;
            float b0 = bias[col], b1 = bias[col + 1];
            float x0 = acc[mt][nt][0] + b0, x1 = acc[mt][nt][1] + b1;
            float x2 = acc[mt][nt][2] + b0, x3 = acc[mt][nt][3] + b1;
            if (OUTMODE == 0) {
                float* C = (float*)Cout;
                *(float2*)&C[(size_t)r0 * N + col] = {x0, x1};
                *(float2*)&C[(size_t)(r0 + 8) * N + col] = {x2, x3};
            } else if (OUTMODE == 1) {
                __half* C = (__half*)Cout;
                uint32_t p0 = h2u(x0, x1), p1 = h2u(x2, x3);
                *(uint32_t*)&C[(size_t)r0 * N + col] = p0;
                *(uint32_t*)&C[(size_t)(r0 + 8) * N + col] = p1;
            } else {
                // V transposed: g_vt[bn*131072 + h*16384 + d*256 + key]
                __half* C = (__half*)Cout;
                int mra = r0, mrb = r0 + 8;
                size_t ba0 = (size_t)(mra >> 8) * 131072 + (size_t)(col >> 6) * 16384
                           + (size_t)(col & 63) * 256 + (mra & 255);
                size_t bb0 = (size_t)(mrb >> 8) * 131072 + (size_t)(col >> 6) * 16384
                           + (size_t)(col & 63) * 256 + (mrb & 255);
                C[ba0] = __float2half_rn(x0);
                C[ba0 + 256] = __float2half_rn(x1);   // (col+1) -> d+1 -> +256
                C[bb0] = __float2half_rn(x2);
                C[bb0 + 256] = __float2half_rn(x3);
            }
        }
    }
}

__global__ __launch_bounds__(128, 2) void qkv_proj_kernel(
    const float* __restrict__ bq, const float* __restrict__ bk,
    const float* __restrict__ bv)
{
    if (blockIdx.z == 0)
        hgemm_body<1>(g_inq, g_wqt, bq, g_qh, 512, 128);
    else if (blockIdx.z == 1)
        hgemm_body<1>(g_ink, g_wkt, bk, g_kh, 512, 128);
    else
        hgemm_body<2>(g_inv, g_wvt, bv, g_vt, 512, 128);
}

__global__ __launch_bounds__(128, 2) void out_proj_kernel(
    const float* __restrict__ bo, float* __restrict__ out)
{
    hgemm_body<0>(g_ao, g_wot, bo, out, 512, 512);
}

// ================= attention: all-fp16 mma, no P staging ====================
// grid (8, 256, 2). 256 threads = 8 warps x 16 q-rows.
// K chunk [64 keys][72h] fp16; V^T chunk [64 d][72h] fp16; double-buffered.
#define AK_STRIDE 72
#define AK_STAGE (64 * AK_STRIDE)      // halves per tensor-stage

__global__ __launch_bounds__(256, 2) void attn_kernel()
{
    __shared__ __half Ksm[2][AK_STAGE];
    __shared__ __half Vsm[2][AK_STAGE];

    int tid = threadIdx.x, lane = tid & 31, warp = tid >> 5;
    int g = lane >> 2, t = lane & 3;

    int h  = blockIdx.x;
    int bn = blockIdx.y;
    int half_ = blockIdx.z;
    size_t baseK  = (size_t)bn * 131072 + (size_t)h * 64;       // g_kh [key][512]
    size_t baseVt = (size_t)bn * 131072 + (size_t)h * 16384;    // g_vt [d][256]
    size_t baseQ  = baseK + (size_t)half_ * 65536;              // g_qh [row][512]

    // cp slots: 1024 16B-chunks per chunk-load (512 K + 512 Vt), 4 per thread
    int slr[4], slc[4], slt[4];
    #pragma unroll
    for (int i = 0; i < 4; i++) {
        int ci = tid + i * 256;
        slt[i] = ci >> 9;
        int w = ci & 511;
        slr[i] = w >> 3; slc[i] = w & 7;
    }

    auto issue = [&](int chunk) {
        if (chunk < 4) {
            int kb = chunk * 64;
            #pragma unroll
            for (int i = 0; i < 4; i++) {
                if (slt[i] == 0) {
                    cp16(smem_u32(&Ksm[chunk & 1][slr[i] * AK_STRIDE + slc[i] * 8]),
                         &g_kh[baseK + (size_t)(kb + slr[i]) * 512 + slc[i] * 8]);
                } else {
                    cp16(smem_u32(&Vsm[chunk & 1][slr[i] * AK_STRIDE + slc[i] * 8]),
                         &g_vt[baseVt + (size_t)slr[i] * 256 + kb + slc[i] * 8]);
                }
            }
        }
        cp_commit();
    };

    issue(0);
    issue(1);

    // Q A-frags direct from gmem, scaled by exact 0.125
    int qr0 = warp * 16;
    const __half2 sc = __float2half2_rn(0.125f);
    uint32_t qa[4][4];
    #pragma unroll
    for (int ks = 0; ks < 4; ks++) {
        size_t r0 = baseQ + (size_t)(qr0 + g) * 512 + 16 * ks + 2 * t;
        size_t r8 = r0 + 8 * 512;
        __half2 v0 = __hmul2(*(const __half2*)&g_qh[r0], sc);
        __half2 v1 = __hmul2(*(const __half2*)&g_qh[r8], sc);
        __half2 v2 = __hmul2(*(const __half2*)&g_qh[r0 + 8], sc);
        __half2 v3 = __hmul2(*(const __half2*)&g_qh[r8 + 8], sc);
        qa[ks][0] = *(uint32_t*)&v0;
        qa[ks][1] = *(uint32_t*)&v1;
        qa[ks][2] = *(uint32_t*)&v2;
        qa[ks][3] = *(uint32_t*)&v3;
    }

    float o[8][4] = {};
    float den0 = 0.0f, den1 = 0.0f;

    #pragma unroll 1
    for (int c = 0; c < 4; c++) {
        cp_wait<1>();
        __syncthreads();
        const __half* Ks = Ksm[c & 1];
        const __half* Vs = Vsm[c & 1];

        // ---- S = Q K^T ----
        float s[8][4] = {};
        #pragma unroll
        for (int ks = 0; ks < 4; ks++) {
            int kb = ks * 16 + 2 * t;      // half offset within row
            uint32_t b[8][2];
            #pragma unroll
            for (int nt = 0; nt < 8; nt++) {
                const __half* rw = Ks + (8 * nt + g) * AK_STRIDE + kb;
                b[nt][0] = *(const uint32_t*)rw;
                b[nt][1] = *(const uint32_t*)(rw + 8);
            }
            #pragma unroll
            for (int nt = 0; nt < 8; nt++)
                mma16(s[nt], qa[ks], b[nt]);
        }

        // ---- exp, denom, pack P into A-frag registers ----
        uint32_t p[8][2];
        #pragma unroll
        for (int nt = 0; nt < 8; nt++) {
            float e0 = __expf(s[nt][0]);
            float e1 = __expf(s[nt][1]);
            float e2 = __expf(s[nt][2]);
            float e3 = __expf(s[nt][3]);
            den0 += e0 + e1;
            den1 += e2 + e3;
            p[nt][0] = h2u(e0, e1);       // row g pair
            p[nt][1] = h2u(e2, e3);       // row g+8 pair
        }

        // ---- O += P V (V^T B-frags) ----
        #pragma unroll
        for (int ks = 0; ks < 4; ks++) {
            uint32_t a[4] = {p[2 * ks][0], p[2 * ks][1],
                             p[2 * ks + 1][0], p[2 * ks + 1][1]};
            int kb = ks * 16 + 2 * t;
            uint32_t b[8][2];
            #pragma unroll
            for (int nt = 0; nt < 8; nt++) {
                const __half* rw = Vs + (8 * nt + g) * AK_STRIDE + kb;
                b[nt][0] = *(const uint32_t*)rw;
                b[nt][1] = *(const uint32_t*)(rw + 8);
            }
            #pragma unroll
            for (int nt = 0; nt < 8; nt++)
                mma16(o[nt], a, b[nt]);
        }

        __syncthreads();
        issue(c + 2);
    }

    den0 += __shfl_xor_sync(0xffffffffu, den0, 1);
    den0 += __shfl_xor_sync(0xffffffffu, den0, 2);
    den1 += __shfl_xor_sync(0xffffffffu, den1, 1);
    den1 += __shfl_xor_sync(0xffffffffu, den1, 2);
    float inv0 = 1.0f / den0, inv1 = 1.0f / den1;

    int rg = qr0 + g;
    #pragma unroll
    for (int nt = 0; nt < 8; nt++) {
        int col = 8 * nt + 2 * t;
        uint32_t h0 = h2u(o[nt][0] * inv0, o[nt][1] * inv0);
        uint32_t h1 = h2u(o[nt][2] * inv1, o[nt][3] * inv1);
        *(uint32_t*)&g_ao[baseQ + (size_t)rg * 512 + col] = h0;
        *(uint32_t*)&g_ao[baseQ + (size_t)(rg + 8) * 512 + col] = h1;
    }
}

extern "C" void kernel_launch(void* const* d_in, const int* in_sizes, int n_in,
                              void* d_out, int out_size)
{
    const float* query = (const float*)d_in[0];
    const float* key   = (const float*)d_in[1];
    const float* value = (const float*)d_in[2];
    const float* Wq    = (const float*)d_in[3];
    const float* bq    = (const float*)d_in[4];
    const float* Wk    = (const float*)d_in[5];
    const float* bk    = (const float*)d_in[6];
    const float* Wv    = (const float*)d_in[7];
    const float* bv    = (const float*)d_in[8];
    const float* Wo    = (const float*)d_in[9];
    const float* bo    = (const float*)d_in[10];
    float* out = (float*)d_out;

    prep_inputs_kernel<<<IN_ELEMS / 1024, 256>>>(query, key, value);
    dim3 tb(32, 32);
    prep_wqkv_kernel<<<dim3(16, 4, 3), tb>>>(Wq, Wk, Wv);
    prep_wo_kernel<<<dim3(16, 16), tb>>>(Wo);

    cudaFuncSetAttribute(qkv_proj_kernel,
                         cudaFuncAttributeMaxDynamicSharedMemorySize, HGEMM_SMEM);
    cudaFuncSetAttribute(out_proj_kernel,
                         cudaFuncAttributeMaxDynamicSharedMemorySize, HGEMM_SMEM);

    dim3 gproj(512 / 128, 65536 / 128, 3);
    qkv_proj_kernel<<<gproj, 128, HGEMM_SMEM>>>(bq, bk, bv);

    dim3 gattn(8, 256, 2);
    attn_kernel<<<gattn, 256>>>();

    dim3 gout(512 / 128, 65536 / 128);
    out_proj_kernel<<<gout, 128, HGEMM_SMEM>>>(bo, out);
}